// round 1
// baseline (speedup 1.0000x reference)
#include <cuda_runtime.h>
#include <cstdint>

// RandomRoll: out[b,c,h,w] = x[b,c,(h - sh) % 512, (w - sw) % 512]
// x: [64, 3, 512, 512] float32 ; shifts: [64, 2] int32
// Pure bandwidth kernel: 192 MiB read + 192 MiB write. Target ~7 TB/s.

static constexpr int H = 512;
static constexpr int W = 512;
static constexpr int HMASK = H - 1;
static constexpr int WMASK = W - 1;
static constexpr int C = 3;

__global__ void __launch_bounds__(256)
random_roll_kernel(const float* __restrict__ x,
                   const int*   __restrict__ shifts,
                   float*       __restrict__ out,
                   int n4)  // number of float4 outputs
{
    int i4 = blockIdx.x * blockDim.x + threadIdx.x;
    if (i4 >= n4) return;

    // Decompose: i4 indexes float4s; 128 float4 per row of 512 floats.
    int w4  = i4 & 127;          // float4 index within row
    int row = i4 >> 7;           // (b*3 + c)*512 + h
    int h   = row & HMASK;
    int bc  = row >> 9;          // b*3 + c
    int b   = bc / 3;            // compiler -> mul-high

    int sh = __ldg(&shifts[2 * b]);
    int sw = __ldg(&shifts[2 * b + 1]);

    int src_h = (h - sh) & HMASK;
    // Source row base (in floats). All offsets < 2^31, int math is safe.
    const float* src = x + (((size_t)(bc << 9 | src_h)) << 9);

    int w0 = w4 << 2;            // first output float column
    float4 v;
    if ((sw & 3) == 0) {
        // Aligned fast path: one LDG.128. Wrap is whole-vector safe because
        // ((w0 - sw) & 511) is a multiple of 4 and +3 never crosses 512.
        int s4 = ((w0 - sw) & WMASK) >> 2;
        v = reinterpret_cast<const float4*>(src)[s4];
    } else {
        // Misaligned: 4 scalar loads with per-element circular wrap.
        // Warp-uniform branch (whole warp shares one row -> one sw).
        v.x = __ldg(&src[(w0     - sw) & WMASK]);
        v.y = __ldg(&src[(w0 + 1 - sw) & WMASK]);
        v.z = __ldg(&src[(w0 + 2 - sw) & WMASK]);
        v.w = __ldg(&src[(w0 + 3 - sw) & WMASK]);
    }

    reinterpret_cast<float4*>(out)[i4] = v;
}

// Scalar tail kernel (defensive; out_size is divisible by 4 for these shapes).
__global__ void random_roll_tail(const float* __restrict__ x,
                                 const int*   __restrict__ shifts,
                                 float*       __restrict__ out,
                                 int start, int total)
{
    int i = start + blockIdx.x * blockDim.x + threadIdx.x;
    if (i >= total) return;
    int w   = i & WMASK;
    int row = i >> 9;
    int h   = row & HMASK;
    int bc  = row >> 9;
    int b   = bc / 3;
    int sh = shifts[2 * b];
    int sw = shifts[2 * b + 1];
    int src_h = (h - sh) & HMASK;
    int src_w = (w - sw) & WMASK;
    out[i] = x[(((size_t)(bc << 9 | src_h)) << 9) + src_w];
}

extern "C" void kernel_launch(void* const* d_in, const int* in_sizes, int n_in,
                              void* d_out, int out_size)
{
    const float* x      = (const float*)d_in[0];
    const int*   shifts = (const int*)d_in[1];
    float*       out    = (float*)d_out;

    int n4 = out_size >> 2;
    if (n4 > 0) {
        int threads = 256;
        int blocks  = (n4 + threads - 1) / threads;
        random_roll_kernel<<<blocks, threads>>>(x, shifts, out, n4);
    }
    int tail_start = n4 << 2;
    int tail = out_size - tail_start;
    if (tail > 0) {
        random_roll_tail<<<(tail + 255) / 256, 256>>>(x, shifts, out, tail_start, out_size);
    }
}

// round 2
// speedup vs baseline: 1.1647x; 1.1647x over previous
#include <cuda_runtime.h>
#include <cstdint>

// RandomRoll: out[b,c,h,w] = x[b,c,(h - sh) & 511, (w - sw) & 511]
// x: [64, 3, 512, 512] fp32; shifts: [64, 2] int32.
// R2: all global loads are aligned LDG.128; W-misalignment is fixed up with
// warp shuffles (lane t needs src vecs v0+t and v0+t+1; neighbor vec comes
// via SHFL.DOWN, lane 31 loads one extra vec). L1 sector traffic ~1x minimum.

static constexpr int HMASK = 511;
static constexpr int WMASK = 511;

__global__ void __launch_bounds__(256)
random_roll_kernel(const float4* __restrict__ x4,
                   const int*    __restrict__ shifts,
                   float4*       __restrict__ out4,
                   int n4)  // number of float4 outputs; caller guarantees n4 % 32 == 0
{
    int i4 = blockIdx.x * blockDim.x + threadIdx.x;
    if (i4 >= n4) return;          // full warps only (n4 multiple of 32)
    int lane = i4 & 31;

    // Decompose output index: 128 float4 per 512-float row.
    int w4  = i4 & 127;            // float4 index within row
    int row = i4 >> 7;             // (b*3 + c)*512 + h
    int h   = row & HMASK;
    int bc  = row >> 9;            // b*3 + c
    int b   = bc / 3;

    int sh = __ldg(&shifts[2 * b]);
    int sw = __ldg(&shifts[2 * b + 1]);

    int src_h = (h - sh) & HMASK;
    const float4* src = x4 + ((size_t)((bc << 9) | src_h) << 7);  // src row base (float4s)

    // Warp-level source window: warp covers output floats [W0, W0+128).
    int W0  = (w4 & ~31) << 2;         // warp's first output float column
    int s0  = (W0 - sw) & WMASK;       // first source float needed by the warp
    int off = s0 & 3;                  // intra-vec misalignment (warp-uniform)
    int v0  = s0 >> 2;                 // first aligned source vec

    float4 o;
    if (off == 0) {
        // Fully aligned: one LDG.128, done.
        o = src[(v0 + lane) & 127];
    } else {
        // Lane t needs elements [off..3] of vec (v0+t) and [0..off-1] of vec (v0+t+1).
        float4 A = src[(v0 + lane) & 127];
        float4 B;
        B.x = __shfl_down_sync(0xffffffffu, A.x, 1);
        B.y = __shfl_down_sync(0xffffffffu, A.y, 1);
        B.z = __shfl_down_sync(0xffffffffu, A.z, 1);
        B.w = __shfl_down_sync(0xffffffffu, A.w, 1);
        if (lane == 31) B = src[(v0 + 32) & 127];  // neighbor vec outside warp
        if (off == 1)      o = make_float4(A.y, A.z, A.w, B.x);
        else if (off == 2) o = make_float4(A.z, A.w, B.x, B.y);
        else               o = make_float4(A.w, B.x, B.y, B.z);
    }

    out4[i4] = o;                      // aligned STG.128
}

// Scalar tail (defensive; out_size divisible by 128 for these shapes).
__global__ void random_roll_tail(const float* __restrict__ x,
                                 const int*   __restrict__ shifts,
                                 float*       __restrict__ out,
                                 int start, int total)
{
    int i = start + blockIdx.x * blockDim.x + threadIdx.x;
    if (i >= total) return;
    int w   = i & WMASK;
    int row = i >> 9;
    int h   = row & HMASK;
    int bc  = row >> 9;
    int b   = bc / 3;
    int sh = shifts[2 * b];
    int sw = shifts[2 * b + 1];
    int src_h = (h - sh) & HMASK;
    int src_w = (w - sw) & WMASK;
    out[i] = x[(((size_t)((bc << 9) | src_h)) << 9) + src_w];
}

extern "C" void kernel_launch(void* const* d_in, const int* in_sizes, int n_in,
                              void* d_out, int out_size)
{
    const float4* x4     = (const float4*)d_in[0];
    const int*    shifts = (const int*)d_in[1];
    float4*       out4   = (float4*)d_out;

    int n4      = out_size >> 2;
    int n4_full = n4 & ~31;            // whole warps only in the vector kernel
    if (n4_full > 0) {
        int threads = 256;
        int blocks  = (n4_full + threads - 1) / threads;
        random_roll_kernel<<<blocks, threads>>>(x4, shifts, out4, n4_full);
    }
    int tail_start = n4_full << 2;
    int tail = out_size - tail_start;
    if (tail > 0) {
        random_roll_tail<<<(tail + 255) / 256, 256>>>((const float*)d_in[0], shifts,
                                                      (float*)d_out, tail_start, out_size);
    }
}

// round 3
// speedup vs baseline: 1.2321x; 1.0579x over previous
#include <cuda_runtime.h>
#include <cstdint>

// RandomRoll: out[b,c,h,w] = x[b,c,(h - sh) & 511, (w - sw) & 511]
// x: [64, 3, 512, 512] fp32; shifts: [64, 2] int32.
// R3: 4 float4 outputs per thread, loads front-batched for MLP=4..5.
// All global loads are aligned LDG.128; W-misalignment fixed with warp
// shuffles (warp-uniform shift per 32-vec window).

static constexpr int HMASK = 511;
static constexpr int WMASK = 511;
static constexpr int VPT   = 4;      // float4s per thread
static constexpr int TPB   = 256;

__global__ void __launch_bounds__(TPB)
random_roll_kernel(const float4* __restrict__ x4,
                   const int*    __restrict__ shifts,
                   float4*       __restrict__ out4,
                   int n4)  // float4 count; caller guarantees n4 % (VPT*TPB) == 0
{
    int lane = threadIdx.x & 31;
    int base = blockIdx.x * (VPT * TPB) + threadIdx.x;

    float4 A[VPT];        // aligned source vec (v0 + lane)
    float4 Bx[VPT];       // lane-31 neighbor vec (v0 + 32), valid on lane 31
    int    off[VPT];      // intra-vec misalignment, warp-uniform
    int    i4s[VPT];

    // ---- Phase 1: index math + all loads, back-to-back ----
    #pragma unroll
    for (int k = 0; k < VPT; k++) {
        int i4 = base + k * TPB;
        i4s[k] = i4;
        int w4  = i4 & 127;          // float4 index within 512-float row
        int row = i4 >> 7;           // (b*3 + c)*512 + h
        int h   = row & HMASK;
        int bc  = row >> 9;
        int b   = bc / 3;

        int sh = __ldg(&shifts[2 * b]);
        int sw = __ldg(&shifts[2 * b + 1]);

        int src_h = (h - sh) & HMASK;
        const float4* src = x4 + ((size_t)((bc << 9) | src_h) << 7);

        int W0 = (w4 & ~31) << 2;        // warp's first output float column
        int s0 = (W0 - sw) & WMASK;      // first source float the warp needs
        off[k] = s0 & 3;
        int v0 = s0 >> 2;

        A[k]  = src[(v0 + lane) & 127];  // aligned LDG.128
        Bx[k] = src[(v0 + 32) & 127];    // neighbor vec (only lane 31 uses it)
    }

    // ---- Phase 2: realign + store ----
    #pragma unroll
    for (int k = 0; k < VPT; k++) {
        float4 o = A[k];
        if (off[k]) {                    // warp-uniform branch
            float4 a = A[k];
            float4 B;
            B.x = __shfl_down_sync(0xffffffffu, a.x, 1);
            B.y = __shfl_down_sync(0xffffffffu, a.y, 1);
            B.z = __shfl_down_sync(0xffffffffu, a.z, 1);
            B.w = __shfl_down_sync(0xffffffffu, a.w, 1);
            if (lane == 31) B = Bx[k];
            if (off[k] == 1)      o = make_float4(a.y, a.z, a.w, B.x);
            else if (off[k] == 2) o = make_float4(a.z, a.w, B.x, B.y);
            else                  o = make_float4(a.w, B.x, B.y, B.z);
        }
        out4[i4s[k]] = o;                // aligned STG.128
    }
}

// Scalar tail (defensive; these shapes divide evenly).
__global__ void random_roll_tail(const float* __restrict__ x,
                                 const int*   __restrict__ shifts,
                                 float*       __restrict__ out,
                                 int start, int total)
{
    int i = start + blockIdx.x * blockDim.x + threadIdx.x;
    if (i >= total) return;
    int w   = i & WMASK;
    int row = i >> 9;
    int h   = row & HMASK;
    int bc  = row >> 9;
    int b   = bc / 3;
    int sh = shifts[2 * b];
    int sw = shifts[2 * b + 1];
    int src_h = (h - sh) & HMASK;
    int src_w = (w - sw) & WMASK;
    out[i] = x[(((size_t)((bc << 9) | src_h)) << 9) + src_w];
}

extern "C" void kernel_launch(void* const* d_in, const int* in_sizes, int n_in,
                              void* d_out, int out_size)
{
    const float4* x4     = (const float4*)d_in[0];
    const int*    shifts = (const int*)d_in[1];
    float4*       out4   = (float4*)d_out;

    int n4       = out_size >> 2;
    int per_blk  = VPT * TPB;                 // 1024 vecs per block
    int n4_full  = (n4 / per_blk) * per_blk;  // whole blocks only
    if (n4_full > 0) {
        random_roll_kernel<<<n4_full / per_blk, TPB>>>(x4, shifts, out4, n4_full);
    }
    int tail_start = n4_full << 2;
    int tail = out_size - tail_start;
    if (tail > 0) {
        random_roll_tail<<<(tail + 255) / 256, 256>>>((const float*)d_in[0], shifts,
                                                      (float*)d_out, tail_start, out_size);
    }
}